// round 4
// baseline (speedup 1.0000x reference)
#include <cuda_runtime.h>
#include <cuda_bf16.h>
#include <cstdint>

#define NNODES 50000
#define NEDGES 800000
#define NGRAPHS 64
#define NEG_SLOPE 0.2f

// ---------------- scratch (static __device__, 16B aligned, no allocation) ---
__device__ __align__(16) float g_h[(size_t)NNODES * 128];
__device__ __align__(16) float g_bufA[(size_t)NNODES * 128];
__device__ __align__(16) float g_bufB[(size_t)NNODES * 128];
__device__ __align__(16) float g_as[NNODES];
__device__ __align__(16) float g_ad[NNODES];
__device__ __align__(16) int g_cnt[NNODES];
__device__ __align__(16) int g_off[NNODES + 1];
__device__ __align__(16) int g_cur[NNODES];
__device__ __align__(16) int g_esrc[NEDGES];   // CSR-ordered src
__device__ __align__(16) int g_src[NEDGES];    // normalized edge src
__device__ __align__(16) int g_dst[NEDGES];    // normalized edge dst
__device__ __align__(16) int g_batch[NNODES];  // normalized batch
__device__ int g_is64;

__device__ __forceinline__ float lrelu(float x) { return x > 0.f ? x : NEG_SLOPE * x; }
__device__ __forceinline__ int clampi(int v, int lo, int hi) {
    return v < lo ? lo : (v > hi ? hi : v);
}

// buffer selection: 0 = g_h, 1 = g_bufA, 2 = g_bufB, 3 = external
__device__ __forceinline__ const float* selbuf_c(int i, const float* ext) {
    if (i == 1) return g_bufA;
    if (i == 2) return g_bufB;
    if (i == 3) return ext;
    return g_h;
}
__device__ __forceinline__ float* selbuf(int i) {
    if (i == 1) return g_bufA;
    if (i == 2) return g_bufB;
    return g_h;
}

// ================= dtype probe + normalization =================
// int64 little-endian: high dword of each element is 0 (all values >= 0, < 50000).
// int32: odd dwords are real edge indices (random in [0, 50000)) -> not all zero.
__global__ void probe_kernel(const int* __restrict__ ei32) {
    if (threadIdx.x == 0 && blockIdx.x == 0) {
        int acc = 0;
        for (int i = 1; i < 64; i += 2) acc |= ei32[i];
        g_is64 = (acc == 0) ? 1 : 0;
    }
}

__global__ void convert_edges_kernel(const void* __restrict__ ei) {
    int e = blockIdx.x * blockDim.x + threadIdx.x;
    if (e >= NEDGES) return;
    int s, d;
    if (g_is64) {
        const long long* p = (const long long*)ei;
        s = (int)p[e];
        d = (int)p[NEDGES + e];
    } else {
        const int* p = (const int*)ei;
        s = p[e];
        d = p[NEDGES + e];
    }
    g_src[e] = clampi(s, 0, NNODES - 1);
    g_dst[e] = clampi(d, 0, NNODES - 1);
}

__global__ void convert_batch_kernel(const void* __restrict__ b) {
    int i = blockIdx.x * blockDim.x + threadIdx.x;
    if (i >= NNODES) return;
    int g;
    if (g_is64) g = (int)((const long long*)b)[i];
    else        g = ((const int*)b)[i];
    g_batch[i] = clampi(g, 0, NGRAPHS - 1);
}

// ================= CSR build =================
__global__ void zero_cnt_kernel() {
    int i = blockIdx.x * blockDim.x + threadIdx.x;
    if (i < NNODES) g_cnt[i] = 0;
}

__global__ void count_kernel() {
    int e = blockIdx.x * blockDim.x + threadIdx.x;
    if (e >= NEDGES) return;
    atomicAdd(&g_cnt[g_dst[e]], 1);
}

// single-block exclusive scan over g_cnt -> g_off, g_cur
__global__ void scan_kernel() {
    __shared__ int partial[1024];
    const int tid = threadIdx.x;
    const int CH = (NNODES + 1023) / 1024;  // 49
    int lo = tid * CH;
    int hi = lo + CH;
    if (lo > NNODES) lo = NNODES;
    if (hi > NNODES) hi = NNODES;
    int sum = 0;
    for (int i = lo; i < hi; i++) sum += g_cnt[i];
    partial[tid] = sum;
    __syncthreads();
#pragma unroll
    for (int off = 1; off < 1024; off <<= 1) {
        int t = (tid >= off) ? partial[tid - off] : 0;
        __syncthreads();
        partial[tid] += t;
        __syncthreads();
    }
    int run = partial[tid] - sum;  // exclusive prefix of this chunk
    for (int i = lo; i < hi; i++) {
        int c = g_cnt[i];
        g_off[i] = run;
        g_cur[i] = run;
        run += c;
    }
    if (tid == 0) g_off[NNODES] = NEDGES;
}

__global__ void scatter_kernel() {
    int e = blockIdx.x * blockDim.x + threadIdx.x;
    if (e >= NEDGES) return;
    int pos = atomicAdd(&g_cur[g_dst[e]], 1);
    if (pos >= 0 && pos < NEDGES) g_esrc[pos] = g_src[e];
}

// ================= GEMM: g_h = A[N,128] @ W[128,dout] =================
template <int BN, int TN>
__global__ void gemm_kernel(int insel, const float* __restrict__ ext,
                            const float* __restrict__ W, int dout) {
    constexpr int BM = 128, BK = 16, TM = 8;
    const float* __restrict__ A = selbuf_c(insel, ext);
    __shared__ __align__(16) float As[BK][BM + 4];
    __shared__ __align__(16) float Bs[BK][BN];
    const int block_row = blockIdx.x * BM;
    const int tid  = threadIdx.x;              // 256
    const int tcol = tid % (BN / TN);
    const int trow = tid / (BN / TN);

    float acc[TM][TN];
#pragma unroll
    for (int i = 0; i < TM; i++)
#pragma unroll
        for (int j = 0; j < TN; j++) acc[i][j] = 0.f;

    for (int k0 = 0; k0 < 128; k0 += BK) {
#pragma unroll
        for (int i = 0; i < 2; i++) {
            int idx = tid + i * 256;
            int m   = idx >> 2;
            int kk  = (idx & 3) * 4;
            int row = block_row + m;
            float4 v = make_float4(0.f, 0.f, 0.f, 0.f);
            if (row < NNODES) v = *(const float4*)(A + (size_t)row * 128 + k0 + kk);
            As[kk + 0][m] = v.x; As[kk + 1][m] = v.y;
            As[kk + 2][m] = v.z; As[kk + 3][m] = v.w;
        }
#pragma unroll
        for (int i = 0; i < (BK * BN) / (256 * 4); i++) {
            int idx = tid + i * 256;
            int r = idx / (BN / 4);
            int c = (idx % (BN / 4)) * 4;
            *(float4*)&Bs[r][c] = *(const float4*)(W + (size_t)(k0 + r) * dout + c);
        }
        __syncthreads();
#pragma unroll
        for (int k = 0; k < BK; k++) {
            float a[TM], b[TN];
            float4 a0 = *(float4*)&As[k][trow * TM];
            float4 a1 = *(float4*)&As[k][trow * TM + 4];
            a[0] = a0.x; a[1] = a0.y; a[2] = a0.z; a[3] = a0.w;
            a[4] = a1.x; a[5] = a1.y; a[6] = a1.z; a[7] = a1.w;
#pragma unroll
            for (int j = 0; j < TN; j += 4) {
                float4 bv = *(float4*)&Bs[k][tcol * TN + j];
                b[j] = bv.x; b[j + 1] = bv.y; b[j + 2] = bv.z; b[j + 3] = bv.w;
            }
#pragma unroll
            for (int i = 0; i < TM; i++)
#pragma unroll
                for (int j = 0; j < TN; j++) acc[i][j] += a[i] * b[j];
        }
        __syncthreads();
    }
#pragma unroll
    for (int i = 0; i < TM; i++) {
        int row = block_row + trow * TM + i;
        if (row < NNODES) {
#pragma unroll
            for (int j = 0; j < TN; j += 4) {
                float4 v = make_float4(acc[i][j], acc[i][j + 1], acc[i][j + 2], acc[i][j + 3]);
                *(float4*)(g_h + (size_t)row * dout + tcol * TN + j) = v;
            }
        }
    }
}

// ================= alpha_src / alpha_dst per node =================
__global__ void alpha_kernel(const float* __restrict__ a_s, const float* __restrict__ a_d,
                             int dout) {
    int node = blockIdx.x * (blockDim.x >> 5) + (threadIdx.x >> 5);
    int lane = threadIdx.x & 31;
    if (node >= NNODES) return;
    float s = 0.f, d = 0.f;
    for (int c = lane; c < dout; c += 32) {
        float v = g_h[(size_t)node * dout + c];
        s += v * __ldg(&a_s[c]);
        d += v * __ldg(&a_d[c]);
    }
#pragma unroll
    for (int o = 16; o; o >>= 1) {
        s += __shfl_xor_sync(0xffffffffu, s, o);
        d += __shfl_xor_sync(0xffffffffu, d, o);
    }
    if (lane == 0) {
        g_as[node] = s;
        g_ad[node] = d;
    }
}

// ===== fused softmax + aggregation + bias + relu : one warp per dst node ====
template <int DOUT>
__launch_bounds__(256)
__global__ void gat_agg_kernel(int outsel, const float* __restrict__ bias, int relu) {
    constexpr int VEC = DOUT / 32;   // floats per lane (4 or 2)
    int n = (blockIdx.x * blockDim.x + threadIdx.x) >> 5;
    int lane = threadIdx.x & 31;
    if (n >= NNODES) return;
    float* __restrict__ out = selbuf(outsel);

    int beg = g_off[n], end = g_off[n + 1];
    float ad_n = g_ad[n];
    float selflogit = lrelu(g_as[n] + ad_n);

    // pass 1: segment max (self loop included)
    float m = selflogit;
    for (int i = beg + lane; i < end; i += 32)
        m = fmaxf(m, lrelu(g_as[g_esrc[i]] + ad_n));
#pragma unroll
    for (int o = 16; o; o >>= 1) m = fmaxf(m, __shfl_xor_sync(0xffffffffu, m, o));

    // pass 2: denom
    float dsum = 0.f;
    for (int i = beg + lane; i < end; i += 32)
        dsum += __expf(lrelu(g_as[g_esrc[i]] + ad_n) - m);
#pragma unroll
    for (int o = 16; o; o >>= 1) dsum += __shfl_xor_sync(0xffffffffu, dsum, o);
    float selfe = __expf(selflogit - m);
    float inv = 1.f / (dsum + selfe);

    // pass 3: aggregate, seeded with the self-loop term
    float acc[VEC];
    {
        float c = selfe * inv;
        if constexpr (VEC == 4) {
            float4 v = *(const float4*)(g_h + (size_t)n * DOUT + lane * 4);
            acc[0] = c * v.x; acc[1] = c * v.y; acc[2] = c * v.z; acc[3] = c * v.w;
        } else {
            float2 v = *(const float2*)(g_h + (size_t)n * DOUT + lane * 2);
            acc[0] = c * v.x; acc[1] = c * v.y;
        }
    }
    for (int base = beg; base < end; base += 32) {
        int cnt = end - base; if (cnt > 32) cnt = 32;
        int src = 0; float coef = 0.f;
        if (lane < cnt) {
            src = g_esrc[base + lane];
            coef = __expf(lrelu(g_as[src] + ad_n) - m) * inv;
        }
        for (int j = 0; j < cnt; j++) {
            int s   = __shfl_sync(0xffffffffu, src, j);
            float c = __shfl_sync(0xffffffffu, coef, j);
            if constexpr (VEC == 4) {
                float4 v = *(const float4*)(g_h + (size_t)s * DOUT + lane * 4);
                acc[0] += c * v.x; acc[1] += c * v.y; acc[2] += c * v.z; acc[3] += c * v.w;
            } else {
                float2 v = *(const float2*)(g_h + (size_t)s * DOUT + lane * 2);
                acc[0] += c * v.x; acc[1] += c * v.y;
            }
        }
    }

    if constexpr (VEC == 4) {
        float4 bv = *(const float4*)(bias + lane * 4);
        acc[0] += bv.x; acc[1] += bv.y; acc[2] += bv.z; acc[3] += bv.w;
        if (relu) {
#pragma unroll
            for (int k = 0; k < 4; k++) acc[k] = fmaxf(acc[k], 0.f);
        }
        *(float4*)(out + (size_t)n * DOUT + lane * 4) =
            make_float4(acc[0], acc[1], acc[2], acc[3]);
    } else {
        float2 bv = *(const float2*)(bias + lane * 2);
        acc[0] += bv.x; acc[1] += bv.y;
        if (relu) { acc[0] = fmaxf(acc[0], 0.f); acc[1] = fmaxf(acc[1], 0.f); }
        *(float2*)(out + (size_t)n * DOUT + lane * 2) = make_float2(acc[0], acc[1]);
    }
}

// ================= global add pool =================
__global__ void zero_out_kernel(float* __restrict__ out, int nelems) {
    int i = blockIdx.x * blockDim.x + threadIdx.x;
    if (i < nelems) out[i] = 0.f;
}

__global__ void pool_kernel(float* __restrict__ out) {
    int idx = blockIdx.x * blockDim.x + threadIdx.x;
    int node = idx >> 6;
    if (node >= NNODES) return;
    int c = idx & 63;
    int g = g_batch[node];
    atomicAdd(out + (size_t)g * 64 + c, g_bufA[(size_t)node * 64 + c]);
}

// ================= host-side layer driver =================
static void run_layer(int insel, const float* ext, const float* W, const float* av,
                      const float* adv, const float* b, int outsel, int dout, bool relu) {
    int gridm = (NNODES + 127) / 128;
    if (dout == 128)
        gemm_kernel<128, 8><<<gridm, 256>>>(insel, ext, W, dout);
    else
        gemm_kernel<64, 4><<<gridm, 256>>>(insel, ext, W, dout);

    alpha_kernel<<<(NNODES + 7) / 8, 256>>>(av, adv, dout);

    int blocks = (NNODES * 32 + 255) / 256;
    if (dout == 128)
        gat_agg_kernel<128><<<blocks, 256>>>(outsel, b, relu ? 1 : 0);
    else
        gat_agg_kernel<64><<<blocks, 256>>>(outsel, b, relu ? 1 : 0);
}

extern "C" void kernel_launch(void* const* d_in, const int* in_sizes, int n_in,
                              void* d_out, int out_size) {
    // ---- size-based input identification (robust to dtype/ordering) ----
    const float* x = nullptr;
    const void* ei = nullptr;
    const void* batch = nullptr;
    const float* W[3] = {nullptr, nullptr, nullptr};
    const float* v128[6] = {0};  // as0, ad0, b0, as1, ad1, b1 (encounter order)
    const float* v64[3]  = {0};  // as2, ad2, b2
    int wi = 0, n128 = 0, n64 = 0;
    for (int i = 0; i < n_in; i++) {
        int sz = in_sizes[i];
        const void* p = d_in[i];
        if (sz == NNODES * 128)      x = (const float*)p;
        else if (sz == 2 * NEDGES)   ei = p;
        else if (sz == NNODES)       batch = p;
        else if (sz == 128 * 128) { if (wi < 2) W[wi++] = (const float*)p; }
        else if (sz == 128 * 64)     W[2] = (const float*)p;
        else if (sz == 128)        { if (n128 < 6) v128[n128++] = (const float*)p; }
        else if (sz == 64)         { if (n64 < 3)  v64[n64++]  = (const float*)p; }
    }

    // ---- normalize int dtype (int32 vs int64), then build CSR ----
    probe_kernel<<<1, 32>>>((const int*)ei);
    convert_edges_kernel<<<(NEDGES + 255) / 256, 256>>>(ei);
    convert_batch_kernel<<<(NNODES + 255) / 256, 256>>>(batch);

    zero_cnt_kernel<<<(NNODES + 255) / 256, 256>>>();
    count_kernel<<<(NEDGES + 255) / 256, 256>>>();
    scan_kernel<<<1, 1024>>>();
    scatter_kernel<<<(NEDGES + 255) / 256, 256>>>();

    // ---- 3 GAT layers ----
    run_layer(3, x, W[0], v128[0], v128[1], v128[2], /*out*/1, 128, true);  // x -> bufA
    run_layer(1, x, W[1], v128[3], v128[4], v128[5], /*out*/2, 128, true);  // bufA -> bufB
    run_layer(2, x, W[2], v64[0],  v64[1],  v64[2],  /*out*/1, 64,  false); // bufB -> bufA

    // ---- global add pool into d_out [64, 64] ----
    float* outp = (float*)d_out;
    zero_out_kernel<<<(out_size + 255) / 256, 256>>>(outp, out_size);
    pool_kernel<<<(NNODES * 64 + 255) / 256, 256>>>(outp);
}

// round 5
// speedup vs baseline: 1.4572x; 1.4572x over previous
#include <cuda_runtime.h>
#include <cuda_bf16.h>
#include <cstdint>

#define NNODES 50000
#define NEDGES 800000
#define NGRAPHS 64
#define NEG_SLOPE 0.2f

// ---------------- scratch (static __device__, 16B aligned, no allocation) ---
__device__ __align__(16) float g_h[(size_t)NNODES * 128];
__device__ __align__(16) float g_bufA[(size_t)NNODES * 128];
__device__ __align__(16) float g_bufB[(size_t)NNODES * 128];
__device__ __align__(16) float g_as[NNODES];
__device__ __align__(16) float g_ad[NNODES];
__device__ __align__(16) int g_cnt[NNODES];
__device__ __align__(16) int g_off[NNODES + 1];
__device__ __align__(16) int g_cur[NNODES];
__device__ __align__(16) int g_esrc[NEDGES];   // CSR-ordered src
__device__ __align__(16) int g_src[NEDGES];    // normalized edge src
__device__ __align__(16) int g_dst[NEDGES];    // normalized edge dst
__device__ __align__(16) int g_batch[NNODES];  // normalized batch
__device__ int g_is64;

__device__ __forceinline__ float lrelu(float x) { return x > 0.f ? x : NEG_SLOPE * x; }
__device__ __forceinline__ int clampi(int v, int lo, int hi) {
    return v < lo ? lo : (v > hi ? hi : v);
}

// buffer selection: 0 = g_h, 1 = g_bufA, 2 = g_bufB, 3 = external
__device__ __forceinline__ const float* selbuf_c(int i, const float* ext) {
    if (i == 1) return g_bufA;
    if (i == 2) return g_bufB;
    if (i == 3) return ext;
    return g_h;
}
__device__ __forceinline__ float* selbuf(int i) {
    if (i == 1) return g_bufA;
    if (i == 2) return g_bufB;
    return g_h;
}

// ================= dtype probe + normalization =================
__global__ void probe_kernel(const int* __restrict__ ei32) {
    if (threadIdx.x == 0 && blockIdx.x == 0) {
        int acc = 0;
        for (int i = 1; i < 64; i += 2) acc |= ei32[i];
        g_is64 = (acc == 0) ? 1 : 0;
    }
}

__global__ void convert_batch_kernel(const void* __restrict__ b) {
    int i = blockIdx.x * blockDim.x + threadIdx.x;
    if (i >= NNODES) return;
    int g;
    if (g_is64) g = (int)((const long long*)b)[i];
    else        g = ((const int*)b)[i];
    g_batch[i] = clampi(g, 0, NGRAPHS - 1);
}

__global__ void zero_cnt_kernel() {
    int i = blockIdx.x * blockDim.x + threadIdx.x;
    if (i < NNODES) g_cnt[i] = 0;
}

// fused: normalize edges + count degree
__global__ void convert_count_kernel(const void* __restrict__ ei) {
    int e = blockIdx.x * blockDim.x + threadIdx.x;
    if (e >= NEDGES) return;
    int s, d;
    if (g_is64) {
        const long long* p = (const long long*)ei;
        s = (int)p[e];
        d = (int)p[NEDGES + e];
    } else {
        const int* p = (const int*)ei;
        s = p[e];
        d = p[NEDGES + e];
    }
    s = clampi(s, 0, NNODES - 1);
    d = clampi(d, 0, NNODES - 1);
    g_src[e] = s;
    g_dst[e] = d;
    atomicAdd(&g_cnt[d], 1);
}

// single-block exclusive scan over g_cnt -> g_off, g_cur
__global__ void scan_kernel() {
    __shared__ int partial[1024];
    const int tid = threadIdx.x;
    const int CH = (NNODES + 1023) / 1024;  // 49
    int lo = tid * CH;
    int hi = lo + CH;
    if (lo > NNODES) lo = NNODES;
    if (hi > NNODES) hi = NNODES;
    int sum = 0;
    for (int i = lo; i < hi; i++) sum += g_cnt[i];
    partial[tid] = sum;
    __syncthreads();
#pragma unroll
    for (int off = 1; off < 1024; off <<= 1) {
        int t = (tid >= off) ? partial[tid - off] : 0;
        __syncthreads();
        partial[tid] += t;
        __syncthreads();
    }
    int run = partial[tid] - sum;
    for (int i = lo; i < hi; i++) {
        int c = g_cnt[i];
        g_off[i] = run;
        g_cur[i] = run;
        run += c;
    }
    if (tid == 0) g_off[NNODES] = NEDGES;
}

__global__ void scatter_kernel() {
    int e = blockIdx.x * blockDim.x + threadIdx.x;
    if (e >= NEDGES) return;
    int pos = atomicAdd(&g_cur[g_dst[e]], 1);
    if (pos >= 0 && pos < NEDGES) g_esrc[pos] = g_src[e];
}

// ================= GEMM: g_h = A[N,128] @ W[128,dout] =================
template <int BN, int TN>
__global__ void gemm_kernel(int insel, const float* __restrict__ ext,
                            const float* __restrict__ W, int dout) {
    constexpr int BM = 128, BK = 16, TM = 8;
    const float* __restrict__ A = selbuf_c(insel, ext);
    __shared__ __align__(16) float As[BK][BM + 4];
    __shared__ __align__(16) float Bs[BK][BN];
    const int block_row = blockIdx.x * BM;
    const int tid  = threadIdx.x;              // 256
    const int tcol = tid % (BN / TN);
    const int trow = tid / (BN / TN);

    float acc[TM][TN];
#pragma unroll
    for (int i = 0; i < TM; i++)
#pragma unroll
        for (int j = 0; j < TN; j++) acc[i][j] = 0.f;

    for (int k0 = 0; k0 < 128; k0 += BK) {
#pragma unroll
        for (int i = 0; i < 2; i++) {
            int idx = tid + i * 256;
            int m   = idx >> 2;
            int kk  = (idx & 3) * 4;
            int row = block_row + m;
            float4 v = make_float4(0.f, 0.f, 0.f, 0.f);
            if (row < NNODES) v = *(const float4*)(A + (size_t)row * 128 + k0 + kk);
            As[kk + 0][m] = v.x; As[kk + 1][m] = v.y;
            As[kk + 2][m] = v.z; As[kk + 3][m] = v.w;
        }
#pragma unroll
        for (int i = 0; i < (BK * BN) / (256 * 4); i++) {
            int idx = tid + i * 256;
            int r = idx / (BN / 4);
            int c = (idx % (BN / 4)) * 4;
            *(float4*)&Bs[r][c] = *(const float4*)(W + (size_t)(k0 + r) * dout + c);
        }
        __syncthreads();
#pragma unroll
        for (int k = 0; k < BK; k++) {
            float a[TM], b[TN];
            float4 a0 = *(float4*)&As[k][trow * TM];
            float4 a1 = *(float4*)&As[k][trow * TM + 4];
            a[0] = a0.x; a[1] = a0.y; a[2] = a0.z; a[3] = a0.w;
            a[4] = a1.x; a[5] = a1.y; a[6] = a1.z; a[7] = a1.w;
#pragma unroll
            for (int j = 0; j < TN; j += 4) {
                float4 bv = *(float4*)&Bs[k][tcol * TN + j];
                b[j] = bv.x; b[j + 1] = bv.y; b[j + 2] = bv.z; b[j + 3] = bv.w;
            }
#pragma unroll
            for (int i = 0; i < TM; i++)
#pragma unroll
                for (int j = 0; j < TN; j++) acc[i][j] += a[i] * b[j];
        }
        __syncthreads();
    }
#pragma unroll
    for (int i = 0; i < TM; i++) {
        int row = block_row + trow * TM + i;
        if (row < NNODES) {
#pragma unroll
            for (int j = 0; j < TN; j += 4) {
                float4 v = make_float4(acc[i][j], acc[i][j + 1], acc[i][j + 2], acc[i][j + 3]);
                *(float4*)(g_h + (size_t)row * dout + tcol * TN + j) = v;
            }
        }
    }
}

// ================= alpha_src / alpha_dst per node =================
__global__ void alpha_kernel(const float* __restrict__ a_s, const float* __restrict__ a_d,
                             int dout) {
    int node = blockIdx.x * (blockDim.x >> 5) + (threadIdx.x >> 5);
    int lane = threadIdx.x & 31;
    if (node >= NNODES) return;
    float s = 0.f, d = 0.f;
    for (int c = lane; c < dout; c += 32) {
        float v = g_h[(size_t)node * dout + c];
        s += v * __ldg(&a_s[c]);
        d += v * __ldg(&a_d[c]);
    }
#pragma unroll
    for (int o = 16; o; o >>= 1) {
        s += __shfl_xor_sync(0xffffffffu, s, o);
        d += __shfl_xor_sync(0xffffffffu, d, o);
    }
    if (lane == 0) {
        g_as[node] = s;
        g_ad[node] = d;
    }
}

// == fused softmax + aggregation + bias + relu, SINGLE edge pass, warp/node ==
// No max-shift: logits are ~N(0,1.6) (max ~8-9 over 850k), exp() cannot
// overflow fp32; the normalization at the end is mathematically identical
// to the max-shifted reference.
template <int DOUT>
__launch_bounds__(256)
__global__ void gat_agg_kernel(int outsel, const float* __restrict__ bias, int relu) {
    constexpr int VEC = DOUT / 32;   // floats per lane (4 or 2)
    int n = (blockIdx.x * blockDim.x + threadIdx.x) >> 5;
    int lane = threadIdx.x & 31;
    if (n >= NNODES) return;
    float* __restrict__ out = selbuf(outsel);

    int beg = g_off[n], end = g_off[n + 1];
    float ad_n = g_ad[n];
    float selfe = __expf(lrelu(g_as[n] + ad_n));

    // accumulators seeded with the self-loop term
    float acc[VEC];
    {
        if constexpr (VEC == 4) {
            float4 v = *(const float4*)(g_h + (size_t)n * DOUT + lane * 4);
            acc[0] = selfe * v.x; acc[1] = selfe * v.y;
            acc[2] = selfe * v.z; acc[3] = selfe * v.w;
        } else {
            float2 v = *(const float2*)(g_h + (size_t)n * DOUT + lane * 2);
            acc[0] = selfe * v.x; acc[1] = selfe * v.y;
        }
    }
    float dpart = (lane == 0) ? selfe : 0.f;  // per-lane partial denominator

    for (int base = beg; base < end; base += 32) {
        int cnt = end - base; if (cnt > 32) cnt = 32;
        int src = 0; float coef = 0.f;
        if (lane < cnt) {
            src = g_esrc[base + lane];
            coef = __expf(lrelu(g_as[src] + ad_n));
        }
        dpart += coef;
        for (int j = 0; j < cnt; j++) {
            int s   = __shfl_sync(0xffffffffu, src, j);
            float c = __shfl_sync(0xffffffffu, coef, j);
            if constexpr (VEC == 4) {
                float4 v = *(const float4*)(g_h + (size_t)s * DOUT + lane * 4);
                acc[0] += c * v.x; acc[1] += c * v.y; acc[2] += c * v.z; acc[3] += c * v.w;
            } else {
                float2 v = *(const float2*)(g_h + (size_t)s * DOUT + lane * 2);
                acc[0] += c * v.x; acc[1] += c * v.y;
            }
        }
    }

    // reduce denominator across warp
#pragma unroll
    for (int o = 16; o; o >>= 1) dpart += __shfl_xor_sync(0xffffffffu, dpart, o);
    float inv = 1.f / dpart;

    if constexpr (VEC == 4) {
        float4 bv = *(const float4*)(bias + lane * 4);
        acc[0] = acc[0] * inv + bv.x; acc[1] = acc[1] * inv + bv.y;
        acc[2] = acc[2] * inv + bv.z; acc[3] = acc[3] * inv + bv.w;
        if (relu) {
#pragma unroll
            for (int k = 0; k < 4; k++) acc[k] = fmaxf(acc[k], 0.f);
        }
        *(float4*)(out + (size_t)n * DOUT + lane * 4) =
            make_float4(acc[0], acc[1], acc[2], acc[3]);
    } else {
        float2 bv = *(const float2*)(bias + lane * 2);
        acc[0] = acc[0] * inv + bv.x; acc[1] = acc[1] * inv + bv.y;
        if (relu) { acc[0] = fmaxf(acc[0], 0.f); acc[1] = fmaxf(acc[1], 0.f); }
        *(float2*)(out + (size_t)n * DOUT + lane * 2) = make_float2(acc[0], acc[1]);
    }
}

// ================= global add pool (batch is sorted -> run-length) ==========
__global__ void zero_out_kernel(float* __restrict__ out, int nelems) {
    int i = blockIdx.x * blockDim.x + threadIdx.x;
    if (i < nelems) out[i] = 0.f;
}

__global__ void pool_kernel(float* __restrict__ out) {
    int idx = blockIdx.x * blockDim.x + threadIdx.x;
    int grp = idx >> 6;          // node group of 8
    int c = idx & 63;
    int n0 = grp * 8;
    if (n0 >= NNODES) return;
    int ncount = NNODES - n0; if (ncount > 8) ncount = 8;
    int curg = g_batch[n0];
    float acc = 0.f;
    for (int k = 0; k < ncount; k++) {
        int g = g_batch[n0 + k];
        float v = g_bufA[(size_t)(n0 + k) * 64 + c];
        if (g != curg) {
            atomicAdd(out + (size_t)curg * 64 + c, acc);
            acc = 0.f; curg = g;
        }
        acc += v;
    }
    atomicAdd(out + (size_t)curg * 64 + c, acc);
}

// ================= host-side layer driver =================
static void run_layer(int insel, const float* ext, const float* W, const float* av,
                      const float* adv, const float* b, int outsel, int dout, bool relu) {
    int gridm = (NNODES + 127) / 128;
    if (dout == 128)
        gemm_kernel<128, 8><<<gridm, 256>>>(insel, ext, W, dout);
    else
        gemm_kernel<64, 4><<<gridm, 256>>>(insel, ext, W, dout);

    alpha_kernel<<<(NNODES + 7) / 8, 256>>>(av, adv, dout);

    int blocks = (NNODES * 32 + 255) / 256;
    if (dout == 128)
        gat_agg_kernel<128><<<blocks, 256>>>(outsel, b, relu ? 1 : 0);
    else
        gat_agg_kernel<64><<<blocks, 256>>>(outsel, b, relu ? 1 : 0);
}

extern "C" void kernel_launch(void* const* d_in, const int* in_sizes, int n_in,
                              void* d_out, int out_size) {
    // ---- size-based input identification (robust to dtype/ordering) ----
    const float* x = nullptr;
    const void* ei = nullptr;
    const void* batch = nullptr;
    const float* W[3] = {nullptr, nullptr, nullptr};
    const float* v128[6] = {0};
    const float* v64[3]  = {0};
    int wi = 0, n128 = 0, n64 = 0;
    for (int i = 0; i < n_in; i++) {
        int sz = in_sizes[i];
        const void* p = d_in[i];
        if (sz == NNODES * 128)      x = (const float*)p;
        else if (sz == 2 * NEDGES)   ei = p;
        else if (sz == NNODES)       batch = p;
        else if (sz == 128 * 128) { if (wi < 2) W[wi++] = (const float*)p; }
        else if (sz == 128 * 64)     W[2] = (const float*)p;
        else if (sz == 128)        { if (n128 < 6) v128[n128++] = (const float*)p; }
        else if (sz == 64)         { if (n64 < 3)  v64[n64++]  = (const float*)p; }
    }

    // ---- normalize dtype + build CSR ----
    probe_kernel<<<1, 32>>>((const int*)ei);
    convert_batch_kernel<<<(NNODES + 255) / 256, 256>>>(batch);
    zero_cnt_kernel<<<(NNODES + 255) / 256, 256>>>();
    convert_count_kernel<<<(NEDGES + 255) / 256, 256>>>(ei);
    scan_kernel<<<1, 1024>>>();
    scatter_kernel<<<(NEDGES + 255) / 256, 256>>>();

    // ---- 3 GAT layers ----
    run_layer(3, x, W[0], v128[0], v128[1], v128[2], /*out*/1, 128, true);
    run_layer(1, x, W[1], v128[3], v128[4], v128[5], /*out*/2, 128, true);
    run_layer(2, x, W[2], v64[0],  v64[1],  v64[2],  /*out*/1, 64,  false);

    // ---- global add pool into d_out [64, 64] ----
    float* outp = (float*)d_out;
    zero_out_kernel<<<(out_size + 255) / 256, 256>>>(outp, out_size);
    pool_kernel<<<((NNODES + 7) / 8 * 64 + 255) / 256, 256>>>(outp);
}

// round 6
// speedup vs baseline: 1.8593x; 1.2760x over previous
#include <cuda_runtime.h>
#include <cuda_bf16.h>
#include <cstdint>

#define NNODES 50000
#define NEDGES 800000
#define NGRAPHS 64
#define NEG_SLOPE 0.2f

// ---------------- scratch (static __device__, 16B aligned, no allocation) ---
__device__ __align__(16) float g_h[(size_t)NNODES * 128];
__device__ __align__(16) float g_bufA[(size_t)NNODES * 128];
__device__ __align__(16) float g_bufB[(size_t)NNODES * 128];
__device__ __align__(16) float g_as[NNODES];
__device__ __align__(16) float g_ad[NNODES];
__device__ __align__(16) int g_cnt[NNODES];
__device__ __align__(16) int g_off[NNODES + 1];
__device__ __align__(16) int g_cur[NNODES];
__device__ __align__(16) int g_esrc[NEDGES];
__device__ __align__(16) int g_src[NEDGES];
__device__ __align__(16) int g_dst[NEDGES];
__device__ __align__(16) int g_batch[NNODES];
__device__ int g_is64;

__device__ __forceinline__ float lrelu(float x) { return x > 0.f ? x : NEG_SLOPE * x; }
__device__ __forceinline__ int clampi(int v, int lo, int hi) {
    return v < lo ? lo : (v > hi ? hi : v);
}

// buffer selection: 0 = g_h, 1 = g_bufA, 2 = g_bufB, 3 = external
__device__ __forceinline__ const float* selbuf_c(int i, const float* ext) {
    if (i == 1) return g_bufA;
    if (i == 2) return g_bufB;
    if (i == 3) return ext;
    return g_h;
}
__device__ __forceinline__ float* selbuf(int i) {
    if (i == 1) return g_bufA;
    if (i == 2) return g_bufB;
    return g_h;
}

// ---------------- tf32 mma helpers ----------------
__device__ __forceinline__ uint32_t f2tf32(float f) {
    uint32_t r;
    asm("cvt.rna.tf32.f32 %0, %1;" : "=r"(r) : "f"(f));
    return r;
}
__device__ __forceinline__ void mma_tf32(float* d, const uint32_t* a, const uint32_t* b) {
    asm volatile(
        "mma.sync.aligned.m16n8k8.row.col.f32.tf32.tf32.f32 "
        "{%0,%1,%2,%3}, {%4,%5,%6,%7}, {%8,%9}, {%0,%1,%2,%3};\n"
        : "+f"(d[0]), "+f"(d[1]), "+f"(d[2]), "+f"(d[3])
        : "r"(a[0]), "r"(a[1]), "r"(a[2]), "r"(a[3]), "r"(b[0]), "r"(b[1]));
}

// ================= dtype probe + normalization =================
__global__ void probe_kernel(const int* __restrict__ ei32) {
    if (threadIdx.x == 0 && blockIdx.x == 0) {
        int acc = 0;
        for (int i = 1; i < 64; i += 2) acc |= ei32[i];
        g_is64 = (acc == 0) ? 1 : 0;
    }
}

__global__ void convert_batch_kernel(const void* __restrict__ b) {
    int i = blockIdx.x * blockDim.x + threadIdx.x;
    if (i >= NNODES) return;
    int g;
    if (g_is64) g = (int)((const long long*)b)[i];
    else        g = ((const int*)b)[i];
    g_batch[i] = clampi(g, 0, NGRAPHS - 1);
}

__global__ void zero_cnt_kernel() {
    int i = blockIdx.x * blockDim.x + threadIdx.x;
    if (i < NNODES) g_cnt[i] = 0;
}

__global__ void convert_count_kernel(const void* __restrict__ ei) {
    int e = blockIdx.x * blockDim.x + threadIdx.x;
    if (e >= NEDGES) return;
    int s, d;
    if (g_is64) {
        const long long* p = (const long long*)ei;
        s = (int)p[e];
        d = (int)p[NEDGES + e];
    } else {
        const int* p = (const int*)ei;
        s = p[e];
        d = p[NEDGES + e];
    }
    s = clampi(s, 0, NNODES - 1);
    d = clampi(d, 0, NNODES - 1);
    g_src[e] = s;
    g_dst[e] = d;
    atomicAdd(&g_cnt[d], 1);
}

__global__ void scan_kernel() {
    __shared__ int partial[1024];
    const int tid = threadIdx.x;
    const int CH = (NNODES + 1023) / 1024;  // 49
    int lo = tid * CH;
    int hi = lo + CH;
    if (lo > NNODES) lo = NNODES;
    if (hi > NNODES) hi = NNODES;
    int sum = 0;
    for (int i = lo; i < hi; i++) sum += g_cnt[i];
    partial[tid] = sum;
    __syncthreads();
#pragma unroll
    for (int off = 1; off < 1024; off <<= 1) {
        int t = (tid >= off) ? partial[tid - off] : 0;
        __syncthreads();
        partial[tid] += t;
        __syncthreads();
    }
    int run = partial[tid] - sum;
    for (int i = lo; i < hi; i++) {
        int c = g_cnt[i];
        g_off[i] = run;
        g_cur[i] = run;
        run += c;
    }
    if (tid == 0) g_off[NNODES] = NEDGES;
}

__global__ void scatter_kernel() {
    int e = blockIdx.x * blockDim.x + threadIdx.x;
    if (e >= NEDGES) return;
    int pos = atomicAdd(&g_cur[g_dst[e]], 1);
    if (pos >= 0 && pos < NEDGES) g_esrc[pos] = g_src[e];
}

// ===== tf32 tensor-core GEMM: g_h[N,BN] = A[N,128] @ W[128,BN] =====
// 256 threads = 8 warps (4x2); warp tile 32 x BN/2; mma m16n8k8.
template <int BN>
__launch_bounds__(256)
__global__ void gemm_tc_kernel(int insel, const float* __restrict__ ext,
                               const float* __restrict__ W) {
    constexpr int BM = 128, BK = 32;
    constexpr int SA = BK + 4;       // As stride (uint32)
    constexpr int SB = BN + 4;       // Bs stride (uint32)
    constexpr int NT = BN / 16;      // n-tiles per warp (8 or 4)
    const float* __restrict__ A = selbuf_c(insel, ext);
    __shared__ __align__(16) uint32_t As[BM * SA];
    __shared__ __align__(16) uint32_t Bs[BK * SB];
    const int tid = threadIdx.x;
    const int lane = tid & 31, warp = tid >> 5;
    const int g = lane >> 2, tig = lane & 3;
    const int wm = (warp & 3) * 32;
    const int wn = (warp >> 2) * (BN / 2);
    const int blockRow = blockIdx.x * BM;

    float acc[2][NT][4];
#pragma unroll
    for (int mt = 0; mt < 2; mt++)
#pragma unroll
        for (int nt = 0; nt < NT; nt++)
#pragma unroll
            for (int k = 0; k < 4; k++) acc[mt][nt][k] = 0.f;

    for (int k0 = 0; k0 < 128; k0 += BK) {
        // A tile: 128 x 32 floats = 1024 float4 slots, 4 per thread
#pragma unroll
        for (int i = 0; i < 4; i++) {
            int s = tid + i * 256;
            int r = s >> 3;
            int c4 = (s & 7) * 4;
            int row = blockRow + r;
            float4 v = make_float4(0.f, 0.f, 0.f, 0.f);
            if (row < NNODES) v = *(const float4*)(A + (size_t)row * 128 + k0 + c4);
            uint4 u = make_uint4(f2tf32(v.x), f2tf32(v.y), f2tf32(v.z), f2tf32(v.w));
            *(uint4*)&As[r * SA + c4] = u;
        }
        // B tile: 32 x BN floats
#pragma unroll
        for (int i = 0; i < (BK * BN / 4) / 256; i++) {
            int s = tid + i * 256;
            int r = s / (BN / 4);
            int c4 = (s % (BN / 4)) * 4;
            float4 v = *(const float4*)(W + (size_t)(k0 + r) * BN + c4);
            uint4 u = make_uint4(f2tf32(v.x), f2tf32(v.y), f2tf32(v.z), f2tf32(v.w));
            *(uint4*)&Bs[r * SB + c4] = u;
        }
        __syncthreads();
#pragma unroll
        for (int kk = 0; kk < BK; kk += 8) {
            uint32_t afr[2][4];
#pragma unroll
            for (int mt = 0; mt < 2; mt++) {
                int r0 = wm + mt * 16 + g;
                afr[mt][0] = As[r0 * SA + kk + tig];
                afr[mt][1] = As[(r0 + 8) * SA + kk + tig];
                afr[mt][2] = As[r0 * SA + kk + tig + 4];
                afr[mt][3] = As[(r0 + 8) * SA + kk + tig + 4];
            }
            uint32_t bfr[NT][2];
#pragma unroll
            for (int nt = 0; nt < NT; nt++) {
                int c = wn + nt * 8 + g;
                bfr[nt][0] = Bs[(kk + tig) * SB + c];
                bfr[nt][1] = Bs[(kk + tig + 4) * SB + c];
            }
#pragma unroll
            for (int mt = 0; mt < 2; mt++)
#pragma unroll
                for (int nt = 0; nt < NT; nt++)
                    mma_tf32(acc[mt][nt], afr[mt], bfr[nt]);
        }
        __syncthreads();
    }
    // epilogue: D fragment rows g/g+8, cols 2*tig/2*tig+1
#pragma unroll
    for (int mt = 0; mt < 2; mt++) {
        int r0 = blockRow + wm + mt * 16 + g;
#pragma unroll
        for (int nt = 0; nt < NT; nt++) {
            int c = wn + nt * 8 + 2 * tig;
            if (r0 < NNODES)
                *(float2*)(g_h + (size_t)r0 * BN + c) =
                    make_float2(acc[mt][nt][0], acc[mt][nt][1]);
            if (r0 + 8 < NNODES)
                *(float2*)(g_h + (size_t)(r0 + 8) * BN + c) =
                    make_float2(acc[mt][nt][2], acc[mt][nt][3]);
        }
    }
}

// ================= alpha_src / alpha_dst per node =================
__global__ void alpha_kernel(const float* __restrict__ a_s, const float* __restrict__ a_d,
                             int dout) {
    int node = blockIdx.x * (blockDim.x >> 5) + (threadIdx.x >> 5);
    int lane = threadIdx.x & 31;
    if (node >= NNODES) return;
    float s = 0.f, d = 0.f;
    for (int c = lane; c < dout; c += 32) {
        float v = g_h[(size_t)node * dout + c];
        s += v * __ldg(&a_s[c]);
        d += v * __ldg(&a_d[c]);
    }
#pragma unroll
    for (int o = 16; o; o >>= 1) {
        s += __shfl_xor_sync(0xffffffffu, s, o);
        d += __shfl_xor_sync(0xffffffffu, d, o);
    }
    if (lane == 0) {
        g_as[node] = s;
        g_ad[node] = d;
    }
}

// == fused softmax + aggregation + bias + relu, single edge pass, warp/node ==
template <int DOUT>
__launch_bounds__(256)
__global__ void gat_agg_kernel(int outsel, const float* __restrict__ bias, int relu) {
    constexpr int VEC = DOUT / 32;
    int n = (blockIdx.x * blockDim.x + threadIdx.x) >> 5;
    int lane = threadIdx.x & 31;
    if (n >= NNODES) return;
    float* __restrict__ out = selbuf(outsel);

    int beg = g_off[n], end = g_off[n + 1];
    float ad_n = g_ad[n];
    float selfe = __expf(lrelu(g_as[n] + ad_n));

    float acc[VEC];
    {
        if constexpr (VEC == 4) {
            float4 v = *(const float4*)(g_h + (size_t)n * DOUT + lane * 4);
            acc[0] = selfe * v.x; acc[1] = selfe * v.y;
            acc[2] = selfe * v.z; acc[3] = selfe * v.w;
        } else {
            float2 v = *(const float2*)(g_h + (size_t)n * DOUT + lane * 2);
            acc[0] = selfe * v.x; acc[1] = selfe * v.y;
        }
    }
    float dpart = (lane == 0) ? selfe : 0.f;

    for (int base = beg; base < end; base += 32) {
        int cnt = end - base; if (cnt > 32) cnt = 32;
        int src = 0; float coef = 0.f;
        if (lane < cnt) {
            src = g_esrc[base + lane];
            coef = __expf(lrelu(g_as[src] + ad_n));
        }
        dpart += coef;
        for (int j = 0; j < cnt; j++) {
            int s   = __shfl_sync(0xffffffffu, src, j);
            float c = __shfl_sync(0xffffffffu, coef, j);
            if constexpr (VEC == 4) {
                float4 v = *(const float4*)(g_h + (size_t)s * DOUT + lane * 4);
                acc[0] += c * v.x; acc[1] += c * v.y; acc[2] += c * v.z; acc[3] += c * v.w;
            } else {
                float2 v = *(const float2*)(g_h + (size_t)s * DOUT + lane * 2);
                acc[0] += c * v.x; acc[1] += c * v.y;
            }
        }
    }

#pragma unroll
    for (int o = 16; o; o >>= 1) dpart += __shfl_xor_sync(0xffffffffu, dpart, o);
    float inv = 1.f / dpart;

    if constexpr (VEC == 4) {
        float4 bv = *(const float4*)(bias + lane * 4);
        acc[0] = acc[0] * inv + bv.x; acc[1] = acc[1] * inv + bv.y;
        acc[2] = acc[2] * inv + bv.z; acc[3] = acc[3] * inv + bv.w;
        if (relu) {
#pragma unroll
            for (int k = 0; k < 4; k++) acc[k] = fmaxf(acc[k], 0.f);
        }
        *(float4*)(out + (size_t)n * DOUT + lane * 4) =
            make_float4(acc[0], acc[1], acc[2], acc[3]);
    } else {
        float2 bv = *(const float2*)(bias + lane * 2);
        acc[0] = acc[0] * inv + bv.x; acc[1] = acc[1] * inv + bv.y;
        if (relu) { acc[0] = fmaxf(acc[0], 0.f); acc[1] = fmaxf(acc[1], 0.f); }
        *(float2*)(out + (size_t)n * DOUT + lane * 2) = make_float2(acc[0], acc[1]);
    }
}

// ================= global add pool (batch sorted -> run-length) ==========
__global__ void zero_out_kernel(float* __restrict__ out, int nelems) {
    int i = blockIdx.x * blockDim.x + threadIdx.x;
    if (i < nelems) out[i] = 0.f;
}

__global__ void pool_kernel(float* __restrict__ out) {
    int idx = blockIdx.x * blockDim.x + threadIdx.x;
    int grp = idx >> 6;
    int c = idx & 63;
    int n0 = grp * 8;
    if (n0 >= NNODES) return;
    int ncount = NNODES - n0; if (ncount > 8) ncount = 8;
    int curg = g_batch[n0];
    float acc = 0.f;
    for (int k = 0; k < ncount; k++) {
        int g = g_batch[n0 + k];
        float v = g_bufA[(size_t)(n0 + k) * 64 + c];
        if (g != curg) {
            atomicAdd(out + (size_t)curg * 64 + c, acc);
            acc = 0.f; curg = g;
        }
        acc += v;
    }
    atomicAdd(out + (size_t)curg * 64 + c, acc);
}

// ================= host-side layer driver =================
static void run_layer(int insel, const float* ext, const float* W, const float* av,
                      const float* adv, const float* b, int outsel, int dout, bool relu) {
    int gridm = (NNODES + 127) / 128;
    if (dout == 128)
        gemm_tc_kernel<128><<<gridm, 256>>>(insel, ext, W);
    else
        gemm_tc_kernel<64><<<gridm, 256>>>(insel, ext, W);

    alpha_kernel<<<(NNODES + 7) / 8, 256>>>(av, adv, dout);

    int blocks = (NNODES * 32 + 255) / 256;
    if (dout == 128)
        gat_agg_kernel<128><<<blocks, 256>>>(outsel, b, relu ? 1 : 0);
    else
        gat_agg_kernel<64><<<blocks, 256>>>(outsel, b, relu ? 1 : 0);
}

extern "C" void kernel_launch(void* const* d_in, const int* in_sizes, int n_in,
                              void* d_out, int out_size) {
    const float* x = nullptr;
    const void* ei = nullptr;
    const void* batch = nullptr;
    const float* W[3] = {nullptr, nullptr, nullptr};
    const float* v128[6] = {0};
    const float* v64[3]  = {0};
    int wi = 0, n128 = 0, n64 = 0;
    for (int i = 0; i < n_in; i++) {
        int sz = in_sizes[i];
        const void* p = d_in[i];
        if (sz == NNODES * 128)      x = (const float*)p;
        else if (sz == 2 * NEDGES)   ei = p;
        else if (sz == NNODES)       batch = p;
        else if (sz == 128 * 128) { if (wi < 2) W[wi++] = (const float*)p; }
        else if (sz == 128 * 64)     W[2] = (const float*)p;
        else if (sz == 128)        { if (n128 < 6) v128[n128++] = (const float*)p; }
        else if (sz == 64)         { if (n64 < 3)  v64[n64++]  = (const float*)p; }
    }

    probe_kernel<<<1, 32>>>((const int*)ei);
    convert_batch_kernel<<<(NNODES + 255) / 256, 256>>>(batch);
    zero_cnt_kernel<<<(NNODES + 255) / 256, 256>>>();
    convert_count_kernel<<<(NEDGES + 255) / 256, 256>>>(ei);
    scan_kernel<<<1, 1024>>>();
    scatter_kernel<<<(NEDGES + 255) / 256, 256>>>();

    run_layer(3, x, W[0], v128[0], v128[1], v128[2], /*out*/1, 128, true);
    run_layer(1, x, W[1], v128[3], v128[4], v128[5], /*out*/2, 128, true);
    run_layer(2, x, W[2], v64[0],  v64[1],  v64[2],  /*out*/1, 64,  false);

    float* outp = (float*)d_out;
    zero_out_kernel<<<(out_size + 255) / 256, 256>>>(outp, out_size);
    pool_kernel<<<((NNODES + 7) / 8 * 64 + 255) / 256, 256>>>(outp);
}

// round 7
// speedup vs baseline: 1.8999x; 1.0218x over previous
#include <cuda_runtime.h>
#include <cuda_fp16.h>
#include <cstdint>

#define NNODES 50000
#define NEDGES 800000
#define NGRAPHS 64
#define NEG_SLOPE 0.2f

// ---------------- scratch (static __device__, 16B aligned, no allocation) ---
__device__ __align__(16) __half2 g_hh[(size_t)NNODES * 64];  // fp16 feature copy
__device__ __align__(16) float g_bufA[(size_t)NNODES * 128];
__device__ __align__(16) float g_bufB[(size_t)NNODES * 128];
__device__ __align__(16) float g_as[NNODES];
__device__ __align__(16) float g_ad[NNODES];
__device__ __align__(16) int g_cnt[NNODES];
__device__ __align__(16) int g_off[NNODES + 1];
__device__ __align__(16) int g_cur[NNODES];
__device__ __align__(16) int g_esrc[NEDGES];
__device__ __align__(16) int g_src[NEDGES];
__device__ __align__(16) int g_dst[NEDGES];
__device__ __align__(16) int g_batch[NNODES];
__device__ int g_is64;

__device__ __forceinline__ float lrelu(float x) { return x > 0.f ? x : NEG_SLOPE * x; }
__device__ __forceinline__ int clampi(int v, int lo, int hi) {
    return v < lo ? lo : (v > hi ? hi : v);
}

// buffer selection for GEMM input: 1 = g_bufA, 2 = g_bufB, 3 = external
__device__ __forceinline__ const float* selbuf_c(int i, const float* ext) {
    if (i == 1) return g_bufA;
    if (i == 2) return g_bufB;
    return ext;
}
__device__ __forceinline__ float* selbuf(int i) {
    if (i == 2) return g_bufB;
    return g_bufA;
}

// ---------------- tf32 mma helpers ----------------
__device__ __forceinline__ uint32_t f2tf32(float f) {
    uint32_t r;
    asm("cvt.rna.tf32.f32 %0, %1;" : "=r"(r) : "f"(f));
    return r;
}
__device__ __forceinline__ void mma_tf32(float* d, const uint32_t* a, const uint32_t* b) {
    asm volatile(
        "mma.sync.aligned.m16n8k8.row.col.f32.tf32.tf32.f32 "
        "{%0,%1,%2,%3}, {%4,%5,%6,%7}, {%8,%9}, {%0,%1,%2,%3};\n"
        : "+f"(d[0]), "+f"(d[1]), "+f"(d[2]), "+f"(d[3])
        : "r"(a[0]), "r"(a[1]), "r"(a[2]), "r"(a[3]), "r"(b[0]), "r"(b[1]));
}

// ================= dtype probe + normalization =================
__global__ void probe_kernel(const int* __restrict__ ei32) {
    if (threadIdx.x == 0 && blockIdx.x == 0) {
        int acc = 0;
        for (int i = 1; i < 64; i += 2) acc |= ei32[i];
        g_is64 = (acc == 0) ? 1 : 0;
    }
}

__global__ void convert_batch_kernel(const void* __restrict__ b) {
    int i = blockIdx.x * blockDim.x + threadIdx.x;
    if (i >= NNODES) return;
    int g;
    if (g_is64) g = (int)((const long long*)b)[i];
    else        g = ((const int*)b)[i];
    g_batch[i] = clampi(g, 0, NGRAPHS - 1);
}

__global__ void zero_cnt_kernel() {
    int i = blockIdx.x * blockDim.x + threadIdx.x;
    if (i < NNODES) g_cnt[i] = 0;
}

__global__ void convert_count_kernel(const void* __restrict__ ei) {
    int e = blockIdx.x * blockDim.x + threadIdx.x;
    if (e >= NEDGES) return;
    int s, d;
    if (g_is64) {
        const long long* p = (const long long*)ei;
        s = (int)p[e];
        d = (int)p[NEDGES + e];
    } else {
        const int* p = (const int*)ei;
        s = p[e];
        d = p[NEDGES + e];
    }
    s = clampi(s, 0, NNODES - 1);
    d = clampi(d, 0, NNODES - 1);
    g_src[e] = s;
    g_dst[e] = d;
    atomicAdd(&g_cnt[d], 1);
}

__global__ void scan_kernel() {
    __shared__ int partial[1024];
    const int tid = threadIdx.x;
    const int CH = (NNODES + 1023) / 1024;  // 49
    int lo = tid * CH;
    int hi = lo + CH;
    if (lo > NNODES) lo = NNODES;
    if (hi > NNODES) hi = NNODES;
    int sum = 0;
    for (int i = lo; i < hi; i++) sum += g_cnt[i];
    partial[tid] = sum;
    __syncthreads();
#pragma unroll
    for (int off = 1; off < 1024; off <<= 1) {
        int t = (tid >= off) ? partial[tid - off] : 0;
        __syncthreads();
        partial[tid] += t;
        __syncthreads();
    }
    int run = partial[tid] - sum;
    for (int i = lo; i < hi; i++) {
        int c = g_cnt[i];
        g_off[i] = run;
        g_cur[i] = run;
        run += c;
    }
    if (tid == 0) g_off[NNODES] = NEDGES;
}

__global__ void scatter_kernel() {
    int e = blockIdx.x * blockDim.x + threadIdx.x;
    if (e >= NEDGES) return;
    int pos = atomicAdd(&g_cur[g_dst[e]], 1);
    if (pos >= 0 && pos < NEDGES) g_esrc[pos] = g_src[e];
}

// ===== tf32 tensor-core GEMM: g_hh[N,BN](fp16) = A[N,128] @ W[128,BN] =====
template <int BN>
__launch_bounds__(256)
__global__ void gemm_tc_kernel(int insel, const float* __restrict__ ext,
                               const float* __restrict__ W) {
    constexpr int BM = 128, BK = 32;
    constexpr int SA = BK + 4;
    constexpr int SB = BN + 4;
    constexpr int NT = BN / 16;
    const float* __restrict__ A = selbuf_c(insel, ext);
    __shared__ __align__(16) uint32_t As[BM * SA];
    __shared__ __align__(16) uint32_t Bs[BK * SB];
    const int tid = threadIdx.x;
    const int lane = tid & 31, warp = tid >> 5;
    const int g = lane >> 2, tig = lane & 3;
    const int wm = (warp & 3) * 32;
    const int wn = (warp >> 2) * (BN / 2);
    const int blockRow = blockIdx.x * BM;

    float acc[2][NT][4];
#pragma unroll
    for (int mt = 0; mt < 2; mt++)
#pragma unroll
        for (int nt = 0; nt < NT; nt++)
#pragma unroll
            for (int k = 0; k < 4; k++) acc[mt][nt][k] = 0.f;

    for (int k0 = 0; k0 < 128; k0 += BK) {
#pragma unroll
        for (int i = 0; i < 4; i++) {
            int s = tid + i * 256;
            int r = s >> 3;
            int c4 = (s & 7) * 4;
            int row = blockRow + r;
            float4 v = make_float4(0.f, 0.f, 0.f, 0.f);
            if (row < NNODES) v = *(const float4*)(A + (size_t)row * 128 + k0 + c4);
            uint4 u = make_uint4(f2tf32(v.x), f2tf32(v.y), f2tf32(v.z), f2tf32(v.w));
            *(uint4*)&As[r * SA + c4] = u;
        }
#pragma unroll
        for (int i = 0; i < (BK * BN / 4) / 256; i++) {
            int s = tid + i * 256;
            int r = s / (BN / 4);
            int c4 = (s % (BN / 4)) * 4;
            float4 v = *(const float4*)(W + (size_t)(k0 + r) * BN + c4);
            uint4 u = make_uint4(f2tf32(v.x), f2tf32(v.y), f2tf32(v.z), f2tf32(v.w));
            *(uint4*)&Bs[r * SB + c4] = u;
        }
        __syncthreads();
#pragma unroll
        for (int kk = 0; kk < BK; kk += 8) {
            uint32_t afr[2][4];
#pragma unroll
            for (int mt = 0; mt < 2; mt++) {
                int r0 = wm + mt * 16 + g;
                afr[mt][0] = As[r0 * SA + kk + tig];
                afr[mt][1] = As[(r0 + 8) * SA + kk + tig];
                afr[mt][2] = As[r0 * SA + kk + tig + 4];
                afr[mt][3] = As[(r0 + 8) * SA + kk + tig + 4];
            }
            uint32_t bfr[NT][2];
#pragma unroll
            for (int nt = 0; nt < NT; nt++) {
                int c = wn + nt * 8 + g;
                bfr[nt][0] = Bs[(kk + tig) * SB + c];
                bfr[nt][1] = Bs[(kk + tig + 4) * SB + c];
            }
#pragma unroll
            for (int mt = 0; mt < 2; mt++)
#pragma unroll
                for (int nt = 0; nt < NT; nt++)
                    mma_tf32(acc[mt][nt], afr[mt], bfr[nt]);
        }
        __syncthreads();
    }
    // epilogue: convert to half2, store fp16 copy only
#pragma unroll
    for (int mt = 0; mt < 2; mt++) {
        int r0 = blockRow + wm + mt * 16 + g;
#pragma unroll
        for (int nt = 0; nt < NT; nt++) {
            int c = wn + nt * 8 + 2 * tig;   // even column
            if (r0 < NNODES)
                g_hh[((size_t)r0 * BN + c) >> 1] =
                    __floats2half2_rn(acc[mt][nt][0], acc[mt][nt][1]);
            if (r0 + 8 < NNODES)
                g_hh[((size_t)(r0 + 8) * BN + c) >> 1] =
                    __floats2half2_rn(acc[mt][nt][2], acc[mt][nt][3]);
        }
    }
}

// ================= alpha_src / alpha_dst per node (reads fp16 copy) =========
__global__ void alpha_kernel(const float* __restrict__ a_s, const float* __restrict__ a_d,
                             int dout) {
    int node = blockIdx.x * (blockDim.x >> 5) + (threadIdx.x >> 5);
    int lane = threadIdx.x & 31;
    if (node >= NNODES) return;
    int half2s = dout >> 1;
    float s = 0.f, d = 0.f;
    for (int c2 = lane; c2 < half2s; c2 += 32) {
        float2 v = __half22float2(g_hh[(size_t)node * half2s + c2]);
        s += v.x * __ldg(&a_s[2 * c2]) + v.y * __ldg(&a_s[2 * c2 + 1]);
        d += v.x * __ldg(&a_d[2 * c2]) + v.y * __ldg(&a_d[2 * c2 + 1]);
    }
#pragma unroll
    for (int o = 16; o; o >>= 1) {
        s += __shfl_xor_sync(0xffffffffu, s, o);
        d += __shfl_xor_sync(0xffffffffu, d, o);
    }
    if (lane == 0) {
        g_as[node] = s;
        g_ad[node] = d;
    }
}

// == fused softmax + aggregation + bias + relu, single edge pass, warp/node ==
// gathers fp16 rows (half traffic), accumulates fp32.
template <int DOUT>
__launch_bounds__(256)
__global__ void gat_agg_kernel(int outsel, const float* __restrict__ bias, int relu) {
    constexpr int VEC = DOUT / 32;       // floats per lane (4 or 2)
    constexpr int H2 = DOUT / 2;         // half2 per row
    int n = (blockIdx.x * blockDim.x + threadIdx.x) >> 5;
    int lane = threadIdx.x & 31;
    if (n >= NNODES) return;
    float* __restrict__ out = selbuf(outsel);

    int beg = g_off[n], end = g_off[n + 1];
    float ad_n = g_ad[n];
    float selfe = __expf(lrelu(g_as[n] + ad_n));

    float acc[VEC];
    {
        if constexpr (VEC == 4) {
            uint2 u = *(const uint2*)(g_hh + (size_t)n * H2 + lane * 2);
            float2 v0 = __half22float2(*(__half2*)&u.x);
            float2 v1 = __half22float2(*(__half2*)&u.y);
            acc[0] = selfe * v0.x; acc[1] = selfe * v0.y;
            acc[2] = selfe * v1.x; acc[3] = selfe * v1.y;
        } else {
            float2 v = __half22float2(g_hh[(size_t)n * H2 + lane]);
            acc[0] = selfe * v.x; acc[1] = selfe * v.y;
        }
    }
    float dpart = (lane == 0) ? selfe : 0.f;

    for (int base = beg; base < end; base += 32) {
        int cnt = end - base; if (cnt > 32) cnt = 32;
        int src = 0; float coef = 0.f;
        if (lane < cnt) {
            src = g_esrc[base + lane];
            coef = __expf(lrelu(g_as[src] + ad_n));
        }
        dpart += coef;
        for (int j = 0; j < cnt; j++) {
            int s   = __shfl_sync(0xffffffffu, src, j);
            float c = __shfl_sync(0xffffffffu, coef, j);
            if constexpr (VEC == 4) {
                uint2 u = *(const uint2*)(g_hh + (size_t)s * H2 + lane * 2);
                float2 v0 = __half22float2(*(__half2*)&u.x);
                float2 v1 = __half22float2(*(__half2*)&u.y);
                acc[0] += c * v0.x; acc[1] += c * v0.y;
                acc[2] += c * v1.x; acc[3] += c * v1.y;
            } else {
                float2 v = __half22float2(g_hh[(size_t)s * H2 + lane]);
                acc[0] += c * v.x; acc[1] += c * v.y;
            }
        }
    }

#pragma unroll
    for (int o = 16; o; o >>= 1) dpart += __shfl_xor_sync(0xffffffffu, dpart, o);
    float inv = 1.f / dpart;

    if constexpr (VEC == 4) {
        float4 bv = *(const float4*)(bias + lane * 4);
        acc[0] = acc[0] * inv + bv.x; acc[1] = acc[1] * inv + bv.y;
        acc[2] = acc[2] * inv + bv.z; acc[3] = acc[3] * inv + bv.w;
        if (relu) {
#pragma unroll
            for (int k = 0; k < 4; k++) acc[k] = fmaxf(acc[k], 0.f);
        }
        *(float4*)(out + (size_t)n * DOUT + lane * 4) =
            make_float4(acc[0], acc[1], acc[2], acc[3]);
    } else {
        float2 bv = *(const float2*)(bias + lane * 2);
        acc[0] = acc[0] * inv + bv.x; acc[1] = acc[1] * inv + bv.y;
        if (relu) { acc[0] = fmaxf(acc[0], 0.f); acc[1] = fmaxf(acc[1], 0.f); }
        *(float2*)(out + (size_t)n * DOUT + lane * 2) = make_float2(acc[0], acc[1]);
    }
}

// ================= global add pool (batch sorted -> run-length) ==========
__global__ void zero_out_kernel(float* __restrict__ out, int nelems) {
    int i = blockIdx.x * blockDim.x + threadIdx.x;
    if (i < nelems) out[i] = 0.f;
}

__global__ void pool_kernel(float* __restrict__ out) {
    int idx = blockIdx.x * blockDim.x + threadIdx.x;
    int grp = idx >> 6;
    int c = idx & 63;
    int n0 = grp * 8;
    if (n0 >= NNODES) return;
    int ncount = NNODES - n0; if (ncount > 8) ncount = 8;
    int curg = g_batch[n0];
    float acc = 0.f;
    for (int k = 0; k < ncount; k++) {
        int g = g_batch[n0 + k];
        float v = g_bufA[(size_t)(n0 + k) * 64 + c];
        if (g != curg) {
            atomicAdd(out + (size_t)curg * 64 + c, acc);
            acc = 0.f; curg = g;
        }
        acc += v;
    }
    atomicAdd(out + (size_t)curg * 64 + c, acc);
}

// ================= host-side layer driver =================
static void run_layer(int insel, const float* ext, const float* W, const float* av,
                      const float* adv, const float* b, int outsel, int dout, bool relu) {
    int gridm = (NNODES + 127) / 128;
    if (dout == 128)
        gemm_tc_kernel<128><<<gridm, 256>>>(insel, ext, W);
    else
        gemm_tc_kernel<64><<<gridm, 256>>>(insel, ext, W);

    alpha_kernel<<<(NNODES + 7) / 8, 256>>>(av, adv, dout);

    int blocks = (NNODES * 32 + 255) / 256;
    if (dout == 128)
        gat_agg_kernel<128><<<blocks, 256>>>(outsel, b, relu ? 1 : 0);
    else
        gat_agg_kernel<64><<<blocks, 256>>>(outsel, b, relu ? 1 : 0);
}

extern "C" void kernel_launch(void* const* d_in, const int* in_sizes, int n_in,
                              void* d_out, int out_size) {
    const float* x = nullptr;
    const void* ei = nullptr;
    const void* batch = nullptr;
    const float* W[3] = {nullptr, nullptr, nullptr};
    const float* v128[6] = {0};
    const float* v64[3]  = {0};
    int wi = 0, n128 = 0, n64 = 0;
    for (int i = 0; i < n_in; i++) {
        int sz = in_sizes[i];
        const void* p = d_in[i];
        if (sz == NNODES * 128)      x = (const float*)p;
        else if (sz == 2 * NEDGES)   ei = p;
        else if (sz == NNODES)       batch = p;
        else if (sz == 128 * 128) { if (wi < 2) W[wi++] = (const float*)p; }
        else if (sz == 128 * 64)     W[2] = (const float*)p;
        else if (sz == 128)        { if (n128 < 6) v128[n128++] = (const float*)p; }
        else if (sz == 64)         { if (n64 < 3)  v64[n64++]  = (const float*)p; }
    }

    probe_kernel<<<1, 32>>>((const int*)ei);
    convert_batch_kernel<<<(NNODES + 255) / 256, 256>>>(batch);
    zero_cnt_kernel<<<(NNODES + 255) / 256, 256>>>();
    convert_count_kernel<<<(NEDGES + 255) / 256, 256>>>(ei);
    scan_kernel<<<1, 1024>>>();
    scatter_kernel<<<(NEDGES + 255) / 256, 256>>>();

    run_layer(3, x, W[0], v128[0], v128[1], v128[2], /*out*/1, 128, true);
    run_layer(1, x, W[1], v128[3], v128[4], v128[5], /*out*/2, 128, true);
    run_layer(2, x, W[2], v64[0],  v64[1],  v64[2],  /*out*/1, 64,  false);

    float* outp = (float*)d_out;
    zero_out_kernel<<<(out_size + 255) / 256, 256>>>(outp, out_size);
    pool_kernel<<<((NNODES + 7) / 8 * 64 + 255) / 256, 256>>>(outp);
}

// round 8
// speedup vs baseline: 1.9548x; 1.0289x over previous
#include <cuda_runtime.h>
#include <cuda_fp16.h>
#include <cstdint>

#define NNODES 50000
#define NEDGES 800000
#define NGRAPHS 64
#define NEG_SLOPE 0.2f

// ---------------- scratch (static __device__, 16B aligned, no allocation) ---
__device__ __align__(16) __half2 g_hh[(size_t)NNODES * 64];  // fp16 feature copy
__device__ __align__(16) float g_bufA[(size_t)NNODES * 128];
__device__ __align__(16) float g_bufB[(size_t)NNODES * 128];
__device__ __align__(16) float g_as[NNODES];
__device__ __align__(16) float g_ad[NNODES];
__device__ __align__(16) int g_cnt[NNODES];
__device__ __align__(16) int g_off[NNODES + 1];
__device__ __align__(16) int g_cur[NNODES];
__device__ __align__(16) int g_esrc[NEDGES];
__device__ __align__(16) int g_src[NEDGES];
__device__ __align__(16) int g_dst[NEDGES];
__device__ __align__(16) int g_batch[NNODES];

__device__ __forceinline__ float lrelu(float x) { return x > 0.f ? x : NEG_SLOPE * x; }
__device__ __forceinline__ int clampi(int v, int lo, int hi) {
    return v < lo ? lo : (v > hi ? hi : v);
}

// buffer selection for GEMM input: 1 = g_bufA, 2 = g_bufB, 3 = external
__device__ __forceinline__ const float* selbuf_c(int i, const float* ext) {
    if (i == 1) return g_bufA;
    if (i == 2) return g_bufB;
    return ext;
}
__device__ __forceinline__ float* selbuf(int i) {
    if (i == 2) return g_bufB;
    return g_bufA;
}

// per-block dtype probe: int64 => high dword of each elem is 0
__device__ __forceinline__ int probe_is64(const int* ei32) {
    int acc = 0;
#pragma unroll
    for (int i = 1; i < 64; i += 2) acc |= __ldg(&ei32[i]);
    return acc == 0;
}

// ---------------- tf32 mma helpers ----------------
__device__ __forceinline__ uint32_t f2tf32(float f) {
    uint32_t r;
    asm("cvt.rna.tf32.f32 %0, %1;" : "=r"(r) : "f"(f));
    return r;
}
__device__ __forceinline__ void mma_tf32(float* d, const uint32_t* a, const uint32_t* b) {
    asm volatile(
        "mma.sync.aligned.m16n8k8.row.col.f32.tf32.tf32.f32 "
        "{%0,%1,%2,%3}, {%4,%5,%6,%7}, {%8,%9}, {%0,%1,%2,%3};\n"
        : "+f"(d[0]), "+f"(d[1]), "+f"(d[2]), "+f"(d[3])
        : "r"(a[0]), "r"(a[1]), "r"(a[2]), "r"(a[3]), "r"(b[0]), "r"(b[1]));
}

// ================= prep: zero g_cnt + convert batch (fused) =================
__global__ void prep_kernel(const int* __restrict__ ei32, const void* __restrict__ batch) {
    __shared__ int s_is64;
    if (threadIdx.x == 0) s_is64 = probe_is64(ei32);
    __syncthreads();
    int is64 = s_is64;
    int i = blockIdx.x * blockDim.x + threadIdx.x;
    if (i < NNODES) {
        g_cnt[i] = 0;
        int g;
        if (is64) g = (int)((const long long*)batch)[i];
        else      g = ((const int*)batch)[i];
        g_batch[i] = clampi(g, 0, NGRAPHS - 1);
    }
}

// ================= convert edges + count degree =================
__global__ void convert_count_kernel(const void* __restrict__ ei) {
    __shared__ int s_is64;
    if (threadIdx.x == 0) s_is64 = probe_is64((const int*)ei);
    __syncthreads();
    int is64 = s_is64;
    int e = blockIdx.x * blockDim.x + threadIdx.x;
    if (e >= NEDGES) return;
    int s, d;
    if (is64) {
        const long long* p = (const long long*)ei;
        s = (int)p[e];
        d = (int)p[NEDGES + e];
    } else {
        const int* p = (const int*)ei;
        s = p[e];
        d = p[NEDGES + e];
    }
    s = clampi(s, 0, NNODES - 1);
    d = clampi(d, 0, NNODES - 1);
    g_src[e] = s;
    g_dst[e] = d;
    atomicAdd(&g_cnt[d], 1);
}

__global__ void scan_kernel() {
    __shared__ int partial[1024];
    const int tid = threadIdx.x;
    const int CH = (NNODES + 1023) / 1024;  // 49
    int lo = tid * CH;
    int hi = lo + CH;
    if (lo > NNODES) lo = NNODES;
    if (hi > NNODES) hi = NNODES;
    int sum = 0;
    for (int i = lo; i < hi; i++) sum += g_cnt[i];
    partial[tid] = sum;
    __syncthreads();
#pragma unroll
    for (int off = 1; off < 1024; off <<= 1) {
        int t = (tid >= off) ? partial[tid - off] : 0;
        __syncthreads();
        partial[tid] += t;
        __syncthreads();
    }
    int run = partial[tid] - sum;
    for (int i = lo; i < hi; i++) {
        int c = g_cnt[i];
        g_off[i] = run;
        g_cur[i] = run;
        run += c;
    }
    if (tid == 0) g_off[NNODES] = NEDGES;
}

__global__ void scatter_kernel() {
    int e = blockIdx.x * blockDim.x + threadIdx.x;
    if (e >= NEDGES) return;
    int pos = atomicAdd(&g_cur[g_dst[e]], 1);
    if (pos >= 0 && pos < NEDGES) g_esrc[pos] = g_src[e];
}

// ===== tf32 GEMM + fused alpha: g_hh(fp16) = A @ W; g_as/g_ad = h.a_s/h.a_d ==
template <int BN>
__launch_bounds__(256)
__global__ void gemm_tc_kernel(int insel, const float* __restrict__ ext,
                               const float* __restrict__ W,
                               const float* __restrict__ a_s,
                               const float* __restrict__ a_d) {
    constexpr int BM = 128, BK = 32;
    constexpr int SA = BK + 4;
    constexpr int SB = BN + 4;
    constexpr int NT = BN / 16;
    const float* __restrict__ A = selbuf_c(insel, ext);
    __shared__ __align__(16) uint32_t As[BM * SA];
    __shared__ __align__(16) uint32_t Bs[BK * SB];
    const int tid = threadIdx.x;
    const int lane = tid & 31, warp = tid >> 5;
    const int g = lane >> 2, tig = lane & 3;
    const int wm = (warp & 3) * 32;
    const int wn = (warp >> 2) * (BN / 2);
    const int blockRow = blockIdx.x * BM;

    float acc[2][NT][4];
#pragma unroll
    for (int mt = 0; mt < 2; mt++)
#pragma unroll
        for (int nt = 0; nt < NT; nt++)
#pragma unroll
            for (int k = 0; k < 4; k++) acc[mt][nt][k] = 0.f;

    for (int k0 = 0; k0 < 128; k0 += BK) {
#pragma unroll
        for (int i = 0; i < 4; i++) {
            int s = tid + i * 256;
            int r = s >> 3;
            int c4 = (s & 7) * 4;
            int row = blockRow + r;
            float4 v = make_float4(0.f, 0.f, 0.f, 0.f);
            if (row < NNODES) v = *(const float4*)(A + (size_t)row * 128 + k0 + c4);
            uint4 u = make_uint4(f2tf32(v.x), f2tf32(v.y), f2tf32(v.z), f2tf32(v.w));
            *(uint4*)&As[r * SA + c4] = u;
        }
#pragma unroll
        for (int i = 0; i < (BK * BN / 4) / 256; i++) {
            int s = tid + i * 256;
            int r = s / (BN / 4);
            int c4 = (s % (BN / 4)) * 4;
            float4 v = *(const float4*)(W + (size_t)(k0 + r) * BN + c4);
            uint4 u = make_uint4(f2tf32(v.x), f2tf32(v.y), f2tf32(v.z), f2tf32(v.w));
            *(uint4*)&Bs[r * SB + c4] = u;
        }
        __syncthreads();
#pragma unroll
        for (int kk = 0; kk < BK; kk += 8) {
            uint32_t afr[2][4];
#pragma unroll
            for (int mt = 0; mt < 2; mt++) {
                int r0 = wm + mt * 16 + g;
                afr[mt][0] = As[r0 * SA + kk + tig];
                afr[mt][1] = As[(r0 + 8) * SA + kk + tig];
                afr[mt][2] = As[r0 * SA + kk + tig + 4];
                afr[mt][3] = As[(r0 + 8) * SA + kk + tig + 4];
            }
            uint32_t bfr[NT][2];
#pragma unroll
            for (int nt = 0; nt < NT; nt++) {
                int c = wn + nt * 8 + g;
                bfr[nt][0] = Bs[(kk + tig) * SB + c];
                bfr[nt][1] = Bs[(kk + tig + 4) * SB + c];
            }
#pragma unroll
            for (int mt = 0; mt < 2; mt++)
#pragma unroll
                for (int nt = 0; nt < NT; nt++)
                    mma_tf32(acc[mt][nt], afr[mt], bfr[nt]);
        }
        __syncthreads();
    }

    // ---- epilogue 1: store fp16 feature copy ----
#pragma unroll
    for (int mt = 0; mt < 2; mt++) {
        int r0 = blockRow + wm + mt * 16 + g;
#pragma unroll
        for (int nt = 0; nt < NT; nt++) {
            int c = wn + nt * 8 + 2 * tig;
            if (r0 < NNODES)
                g_hh[((size_t)r0 * BN + c) >> 1] =
                    __floats2half2_rn(acc[mt][nt][0], acc[mt][nt][1]);
            if (r0 + 8 < NNODES)
                g_hh[((size_t)(r0 + 8) * BN + c) >> 1] =
                    __floats2half2_rn(acc[mt][nt][2], acc[mt][nt][3]);
        }
    }

    // ---- epilogue 2: fused alpha (block holds the full h row) ----
    float* sA = (float*)As;            // reuse smem: [0,BM) = s, [BM,2BM) = d
    if (tid < BM) { sA[tid] = 0.f; sA[BM + tid] = 0.f; }
    __syncthreads();
#pragma unroll
    for (int mt = 0; mt < 2; mt++) {
        int lr = wm + mt * 16 + g;     // local rows lr, lr+8
        float s0 = 0.f, d0 = 0.f, s1 = 0.f, d1 = 0.f;
#pragma unroll
        for (int nt = 0; nt < NT; nt++) {
            int c = wn + nt * 8 + 2 * tig;
            float as0 = __ldg(&a_s[c]), as1 = __ldg(&a_s[c + 1]);
            float ad0 = __ldg(&a_d[c]), ad1 = __ldg(&a_d[c + 1]);
            s0 += acc[mt][nt][0] * as0 + acc[mt][nt][1] * as1;
            d0 += acc[mt][nt][0] * ad0 + acc[mt][nt][1] * ad1;
            s1 += acc[mt][nt][2] * as0 + acc[mt][nt][3] * as1;
            d1 += acc[mt][nt][2] * ad0 + acc[mt][nt][3] * ad1;
        }
        atomicAdd(&sA[lr], s0);      atomicAdd(&sA[BM + lr], d0);
        atomicAdd(&sA[lr + 8], s1);  atomicAdd(&sA[BM + lr + 8], d1);
    }
    __syncthreads();
    if (tid < BM) {
        int row = blockRow + tid;
        if (row < NNODES) {
            g_as[row] = sA[tid];
            g_ad[row] = sA[BM + tid];
        }
    }
}

// == fused softmax + aggregation + bias + relu, single edge pass, warp/node ==
template <int DOUT>
__launch_bounds__(256)
__global__ void gat_agg_kernel(int outsel, const float* __restrict__ bias, int relu) {
    constexpr int VEC = DOUT / 32;
    constexpr int H2 = DOUT / 2;
    int n = (blockIdx.x * blockDim.x + threadIdx.x) >> 5;
    int lane = threadIdx.x & 31;
    if (n >= NNODES) return;
    float* __restrict__ out = selbuf(outsel);

    int beg = g_off[n], end = g_off[n + 1];
    float ad_n = g_ad[n];
    float selfe = __expf(lrelu(g_as[n] + ad_n));

    float acc[VEC];
    {
        if constexpr (VEC == 4) {
            uint2 u = *(const uint2*)(g_hh + (size_t)n * H2 + lane * 2);
            float2 v0 = __half22float2(*(__half2*)&u.x);
            float2 v1 = __half22float2(*(__half2*)&u.y);
            acc[0] = selfe * v0.x; acc[1] = selfe * v0.y;
            acc[2] = selfe * v1.x; acc[3] = selfe * v1.y;
        } else {
            float2 v = __half22float2(g_hh[(size_t)n * H2 + lane]);
            acc[0] = selfe * v.x; acc[1] = selfe * v.y;
        }
    }
    float dpart = (lane == 0) ? selfe : 0.f;

    for (int base = beg; base < end; base += 32) {
        int cnt = end - base; if (cnt > 32) cnt = 32;
        int src = 0; float coef = 0.f;
        if (lane < cnt) {
            src = g_esrc[base + lane];
            coef = __expf(lrelu(g_as[src] + ad_n));
        }
        dpart += coef;
        for (int j = 0; j < cnt; j++) {
            int s   = __shfl_sync(0xffffffffu, src, j);
            float c = __shfl_sync(0xffffffffu, coef, j);
            if constexpr (VEC == 4) {
                uint2 u = *(const uint2*)(g_hh + (size_t)s * H2 + lane * 2);
                float2 v0 = __half22float2(*(__half2*)&u.x);
                float2 v1 = __half22float2(*(__half2*)&u.y);
                acc[0] += c * v0.x; acc[1] += c * v0.y;
                acc[2] += c * v1.x; acc[3] += c * v1.y;
            } else {
                float2 v = __half22float2(g_hh[(size_t)s * H2 + lane]);
                acc[0] += c * v.x; acc[1] += c * v.y;
            }
        }
    }

#pragma unroll
    for (int o = 16; o; o >>= 1) dpart += __shfl_xor_sync(0xffffffffu, dpart, o);
    float inv = 1.f / dpart;

    if constexpr (VEC == 4) {
        float4 bv = *(const float4*)(bias + lane * 4);
        acc[0] = acc[0] * inv + bv.x; acc[1] = acc[1] * inv + bv.y;
        acc[2] = acc[2] * inv + bv.z; acc[3] = acc[3] * inv + bv.w;
        if (relu) {
#pragma unroll
            for (int k = 0; k < 4; k++) acc[k] = fmaxf(acc[k], 0.f);
        }
        *(float4*)(out + (size_t)n * DOUT + lane * 4) =
            make_float4(acc[0], acc[1], acc[2], acc[3]);
    } else {
        float2 bv = *(const float2*)(bias + lane * 2);
        acc[0] = acc[0] * inv + bv.x; acc[1] = acc[1] * inv + bv.y;
        if (relu) { acc[0] = fmaxf(acc[0], 0.f); acc[1] = fmaxf(acc[1], 0.f); }
        *(float2*)(out + (size_t)n * DOUT + lane * 2) = make_float2(acc[0], acc[1]);
    }
}

// ================= global add pool (batch sorted -> run-length) ==========
__global__ void zero_out_kernel(float* __restrict__ out, int nelems) {
    int i = blockIdx.x * blockDim.x + threadIdx.x;
    if (i < nelems) out[i] = 0.f;
}

__global__ void pool_kernel(float* __restrict__ out) {
    int idx = blockIdx.x * blockDim.x + threadIdx.x;
    int grp = idx >> 6;
    int c = idx & 63;
    int n0 = grp * 8;
    if (n0 >= NNODES) return;
    int ncount = NNODES - n0; if (ncount > 8) ncount = 8;
    int curg = g_batch[n0];
    float acc = 0.f;
    for (int k = 0; k < ncount; k++) {
        int g = g_batch[n0 + k];
        float v = g_bufA[(size_t)(n0 + k) * 64 + c];
        if (g != curg) {
            atomicAdd(out + (size_t)curg * 64 + c, acc);
            acc = 0.f; curg = g;
        }
        acc += v;
    }
    atomicAdd(out + (size_t)curg * 64 + c, acc);
}

// ================= host-side layer driver =================
static void run_layer(int insel, const float* ext, const float* W, const float* av,
                      const float* adv, const float* b, int outsel, int dout, bool relu) {
    int gridm = (NNODES + 127) / 128;
    if (dout == 128)
        gemm_tc_kernel<128><<<gridm, 256>>>(insel, ext, W, av, adv);
    else
        gemm_tc_kernel<64><<<gridm, 256>>>(insel, ext, W, av, adv);

    int blocks = (NNODES * 32 + 255) / 256;
    if (dout == 128)
        gat_agg_kernel<128><<<blocks, 256>>>(outsel, b, relu ? 1 : 0);
    else
        gat_agg_kernel<64><<<blocks, 256>>>(outsel, b, relu ? 1 : 0);
}

extern "C" void kernel_launch(void* const* d_in, const int* in_sizes, int n_in,
                              void* d_out, int out_size) {
    const float* x = nullptr;
    const void* ei = nullptr;
    const void* batch = nullptr;
    const float* W[3] = {nullptr, nullptr, nullptr};
    const float* v128[6] = {0};
    const float* v64[3]  = {0};
    int wi = 0, n128 = 0, n64 = 0;
    for (int i = 0; i < n_in; i++) {
        int sz = in_sizes[i];
        const void* p = d_in[i];
        if (sz == NNODES * 128)      x = (const float*)p;
        else if (sz == 2 * NEDGES)   ei = p;
        else if (sz == NNODES)       batch = p;
        else if (sz == 128 * 128) { if (wi < 2) W[wi++] = (const float*)p; }
        else if (sz == 128 * 64)     W[2] = (const float*)p;
        else if (sz == 128)        { if (n128 < 6) v128[n128++] = (const float*)p; }
        else if (sz == 64)         { if (n64 < 3)  v64[n64++]  = (const float*)p; }
    }

    prep_kernel<<<(NNODES + 255) / 256, 256>>>((const int*)ei, batch);
    convert_count_kernel<<<(NEDGES + 255) / 256, 256>>>(ei);
    scan_kernel<<<1, 1024>>>();
    scatter_kernel<<<(NEDGES + 255) / 256, 256>>>();

    run_layer(3, x, W[0], v128[0], v128[1], v128[2], /*out*/1, 128, true);
    run_layer(1, x, W[1], v128[3], v128[4], v128[5], /*out*/2, 128, true);
    run_layer(2, x, W[2], v64[0],  v64[1],  v64[2],  /*out*/1, 64,  false);

    float* outp = (float*)d_out;
    zero_out_kernel<<<(out_size + 255) / 256, 256>>>(outp, out_size);
    pool_kernel<<<((NNODES + 7) / 8 * 64 + 255) / 256, 256>>>(outp);
}